// round 9
// baseline (speedup 1.0000x reference)
#include <cuda_runtime.h>

// R2D2Head: B tasks (2048), s=25 support, d=640, 5-way, q=75 queries
#define NS 25
#define DQ 640
#define NWAY 5
#define NQ 75
#define RIDGE 50.0f
#define TASKS_MAX 2048
#define NCHUNK 4

#define SR 640     // S smem row stride
#define ACOLS 33   // augmented matrix row stride (conflict-free columns)
#define WS 640     // W_T smem row stride in kernel B

__device__ float g_W[TASKS_MAX * NWAY * DQ];   // 26.2 MB scratch

// packed fp32x2 FMA (FFMA2) — only reachable via PTX
__device__ __forceinline__ void fma_f32x2(unsigned long long& acc,
                                          unsigned long long a,
                                          unsigned long long b)
{
    asm("fma.rn.f32x2 %0, %1, %2, %0;" : "+l"(acc) : "l"(a), "l"(b));
}

// ---------------- Kernel A: gram + solve + W ----------------
// smem: S 16000 | A 25*33=825 | SOL 200 | FLAG 4 -> 17032 floats (68.1 KB), 3 CTAs/SM
#define A_OFF_S    0
#define A_OFF_A    16000
#define A_OFF_SOL  16828
#define A_OFF_FLAG 17028
#define A_SMEM_FLOATS 17032

__global__ __launch_bounds__(256, 3)
void r2d2_prep(const float* __restrict__ support,
               const int* __restrict__ labels_raw,
               int task_base)
{
    extern __shared__ float sm[];
    float* Ssm = sm + A_OFF_S;
    float* A   = sm + A_OFF_A;
    float* SOL = sm + A_OFF_SOL;
    int*  FLAG = (int*)(sm + A_OFF_FLAG);

    const int b = task_base + blockIdx.x;
    const int t = threadIdx.x;
    const int warp = t >> 5, lane = t & 31;

    // ---- label dtype sniff: parallel, one load latency ----
    if (warp == 0) {
        int lo = labels_raw[2 * lane];
        int hi = labels_raw[2 * lane + 1];
        bool ok = (hi == 0) && (lo >= 0) && (lo <= 4);
        unsigned m = __ballot_sync(0xffffffffu, ok);
        if (lane == 0) FLAG[0] = (m == 0xffffffffu) ? 1 : 0;
    }

    // ---- load S (25 x 640) via float4, streaming hint ----
    const float4* Sg4 = (const float4*)(support + (size_t)b * NS * DQ);
    float4* Ss4 = (float4*)Ssm;
    for (int idx = t; idx < NS * DQ / 4; idx += 256)
        Ss4[idx] = __ldcs(&Sg4[idx]);
    __syncthreads();

    const int lab_i64 = FLAG[0];

    // ---- gram: warp per 5x5 triangular tile, packed f32x2 FMA ----
    for (int tile = warp; tile < 15; tile += 8) {
        int ti = 0, rem = tile;
        while (rem >= 5 - ti) { rem -= 5 - ti; ++ti; }
        int tj = ti + rem;

        unsigned long long acc2[5][5];
        #pragma unroll
        for (int r = 0; r < 5; ++r)
            #pragma unroll
            for (int c = 0; c < 5; ++c) acc2[r][c] = 0ull;

        const float* Ri = Ssm + (5 * ti) * SR;
        const float* Rj = Ssm + (5 * tj) * SR;
        #pragma unroll 1
        for (int it = 0; it < 10; ++it) {       // 10 * 64 = 640 (2 floats/lane)
            int off = 2 * lane + 64 * it;
            unsigned long long av[5], bv[5];
            #pragma unroll
            for (int r = 0; r < 5; ++r)
                av[r] = *(const unsigned long long*)(Ri + r * SR + off);
            #pragma unroll
            for (int c = 0; c < 5; ++c)
                bv[c] = *(const unsigned long long*)(Rj + c * SR + off);
            #pragma unroll
            for (int r = 0; r < 5; ++r)
                #pragma unroll
                for (int c = 0; c < 5; ++c)
                    fma_f32x2(acc2[r][c], av[r], bv[c]);
        }
        #pragma unroll
        for (int r = 0; r < 5; ++r)
            #pragma unroll
            for (int c = 0; c < 5; ++c) {
                float2 p = *reinterpret_cast<float2*>(&acc2[r][c]);
                float v = p.x + p.y;
                v += __shfl_down_sync(0xffffffffu, v, 16);
                v += __shfl_down_sync(0xffffffffu, v, 8);
                v += __shfl_down_sync(0xffffffffu, v, 4);
                v += __shfl_down_sync(0xffffffffu, v, 2);
                v += __shfl_down_sync(0xffffffffu, v, 1);
                if (lane == 0) {
                    int i = 5 * ti + r, j = 5 * tj + c;
                    float g = v + (i == j ? RIDGE : 0.f);
                    A[i * ACOLS + j] = g;
                    A[j * ACOLS + i] = g;
                }
            }
    }
    // one-hot Y into columns 25..29
    if (t < 125) {
        int i = t / 5, w = t - i * 5;
        int base = b * NS + i;
        int lab = lab_i64 ? labels_raw[2 * base] : labels_raw[base];
        A[i * ACOLS + 25 + w] = (lab == w) ? 1.f : 0.f;
    }
    __syncthreads();

    // ---- solve: block-parallel Gauss-Jordan (REVERT: measured-best) ----
    {
        const int gi = t % 25;
        const int gj = t / 25;            // 0..9 active
        const bool act = (t < 250);
        for (int k = 0; k < NS; ++k) {
            float f = 0.f, pk0 = 0.f, pk1 = 0.f, pk2 = 0.f;
            if (act) {
                f   = A[gi * ACOLS + k] / A[k * ACOLS + k];
                pk0 = A[k * ACOLS + gj];
                pk1 = A[k * ACOLS + gj + 10];
                pk2 = A[k * ACOLS + gj + 20];
            }
            __syncthreads();
            if (act && gi != k) {
                A[gi * ACOLS + gj]      -= f * pk0;
                A[gi * ACOLS + gj + 10] -= f * pk1;
                A[gi * ACOLS + gj + 20] -= f * pk2;
            }
            __syncthreads();
        }
    }
    if (t < 125) {
        int i = t / 5, w = t - i * 5;
        SOL[i * 8 + w] = A[i * ACOLS + 25 + w] / A[i * ACOLS + i];
    }
    __syncthreads();

    // ---- W[w][d] = sum_s S[s][d] * sol[s][w]  -> global scratch ----
    {
        float* Wb = g_W + (size_t)b * NWAY * DQ;
        int d0 = t, d1 = t + 256, d2 = t + 512;
        bool h2 = (d2 < DQ);
        float a0[5], a1[5], a2[5];
        #pragma unroll
        for (int w = 0; w < 5; ++w) { a0[w] = 0.f; a1[w] = 0.f; a2[w] = 0.f; }
        for (int s = 0; s < NS; ++s) {
            float s0 = Ssm[s * SR + d0];
            float s1 = Ssm[s * SR + d1];
            float s2 = h2 ? Ssm[s * SR + d2] : 0.f;
            #pragma unroll
            for (int w = 0; w < 5; ++w) {
                float sv = SOL[s * 8 + w];
                a0[w] = fmaf(s0, sv, a0[w]);
                a1[w] = fmaf(s1, sv, a1[w]);
                a2[w] = fmaf(s2, sv, a2[w]);
            }
        }
        #pragma unroll
        for (int w = 0; w < 5; ++w) {
            Wb[w * DQ + d0] = a0[w];
            Wb[w * DQ + d1] = a1[w];
            if (h2) Wb[w * DQ + d2] = a2[w];
        }
    }
}

// ---------------- Kernel B: logits = Q @ W (64-reg, 4 CTAs/SM) ----------------
#define B_OFF_WT  0
#define B_OFF_LOG 3200
#define B_SMEM_FLOATS 3576

__global__ __launch_bounds__(256, 4)
void r2d2_logits(const float* __restrict__ query,
                 float* __restrict__ out,
                 int task_base)
{
    extern __shared__ float sm[];
    float* WT  = sm + B_OFF_WT;
    float* LOG = sm + B_OFF_LOG;

    const int b = task_base + blockIdx.x;
    const int t = threadIdx.x;
    const int warp = t >> 5, lane = t & 31;

    {
        const float4* Wg4 = (const float4*)(g_W + (size_t)b * NWAY * DQ);
        float4* Wt4 = (float4*)WT;
        for (int idx = t; idx < NWAY * DQ / 4; idx += 256)
            Wt4[idx] = Wg4[idx];
    }
    __syncthreads();

    const float4* Qb = (const float4*)(query + (size_t)b * NQ * DQ);
    for (int g = warp; g < 15; g += 8) {
        int r0 = g * 5;
        float acc[5][5];
        #pragma unroll
        for (int r = 0; r < 5; ++r)
            #pragma unroll
            for (int w = 0; w < 5; ++w) acc[r][w] = 0.f;

        #pragma unroll
        for (int it = 0; it < 5; ++it) {
            int d4 = lane + it * 32;
            float4 qv[5];
            #pragma unroll
            for (int r = 0; r < 5; ++r) qv[r] = __ldcs(&Qb[(r0 + r) * 160 + d4]);
            #pragma unroll
            for (int w = 0; w < 5; ++w) {
                float4 wv = *(const float4*)&WT[w * WS + d4 * 4];
                #pragma unroll
                for (int r = 0; r < 5; ++r) {
                    acc[r][w] = fmaf(qv[r].x, wv.x, acc[r][w]);
                    acc[r][w] = fmaf(qv[r].y, wv.y, acc[r][w]);
                    acc[r][w] = fmaf(qv[r].z, wv.z, acc[r][w]);
                    acc[r][w] = fmaf(qv[r].w, wv.w, acc[r][w]);
                }
            }
        }
        #pragma unroll
        for (int r = 0; r < 5; ++r)
            #pragma unroll
            for (int w = 0; w < 5; ++w) {
                float v = acc[r][w];
                v += __shfl_xor_sync(0xffffffffu, v, 16);
                v += __shfl_xor_sync(0xffffffffu, v, 8);
                v += __shfl_xor_sync(0xffffffffu, v, 4);
                v += __shfl_xor_sync(0xffffffffu, v, 2);
                v += __shfl_xor_sync(0xffffffffu, v, 1);
                acc[r][w] = v;
            }
        if (lane == 0) {
            #pragma unroll
            for (int r = 0; r < 5; ++r)
                #pragma unroll
                for (int w = 0; w < 5; ++w)
                    LOG[(r0 + r) * 5 + w] = acc[r][w];
        }
    }
    __syncthreads();

    for (int idx = t; idx < NQ * NWAY; idx += 256)
        out[(size_t)b * (NQ * NWAY) + idx] = LOG[idx];
}

extern "C" void kernel_launch(void* const* d_in, const int* in_sizes, int n_in,
                              void* d_out, int out_size)
{
    const float* query   = (const float*)d_in[0];
    const float* support = (const float*)d_in[1];
    const int* labels    = (const int*)d_in[2];
    float* out = (float*)d_out;

    int tasks = in_sizes[1] / (NS * DQ);
    if (tasks > TASKS_MAX) tasks = TASKS_MAX;

    // one-time host-side handles (created on the eager correctness call,
    // reused under graph capture; identical work every call)
    static cudaStream_t s_b = 0;
    static cudaEvent_t evA[NCHUNK];
    static cudaEvent_t evJoin = 0;
    if (s_b == 0) {
        cudaStreamCreateWithFlags(&s_b, cudaStreamNonBlocking);
        for (int i = 0; i < NCHUNK; ++i)
            cudaEventCreateWithFlags(&evA[i], cudaEventDisableTiming);
        cudaEventCreateWithFlags(&evJoin, cudaEventDisableTiming);

        size_t smemA = (size_t)A_SMEM_FLOATS * sizeof(float);
        cudaFuncSetAttribute(r2d2_prep,
                             cudaFuncAttributeMaxDynamicSharedMemorySize,
                             (int)smemA);
    }

    const size_t smemA = (size_t)A_SMEM_FLOATS * sizeof(float);
    const size_t smemB = (size_t)B_SMEM_FLOATS * sizeof(float);

    const int chunk = (tasks + NCHUNK - 1) / NCHUNK;

    // A chunks on the main (capture) stream, each followed by an event
    for (int i = 0; i < NCHUNK; ++i) {
        int base = i * chunk;
        int n = tasks - base; if (n > chunk) n = chunk;
        if (n <= 0) { cudaEventRecord(evA[i], 0); continue; }
        r2d2_prep<<<n, 256, smemA>>>(support, labels, base);
        cudaEventRecord(evA[i], 0);
    }

    // B chunks on the side stream, each gated on its A chunk
    for (int i = 0; i < NCHUNK; ++i) {
        int base = i * chunk;
        int n = tasks - base; if (n > chunk) n = chunk;
        cudaStreamWaitEvent(s_b, evA[i], 0);
        if (n <= 0) continue;
        r2d2_logits<<<n, 256, smemB, s_b>>>(query, out, base);
    }

    // join side stream back into the main stream
    cudaEventRecord(evJoin, s_b);
    cudaStreamWaitEvent(0, evJoin, 0);
}

// round 10
// speedup vs baseline: 1.1484x; 1.1484x over previous
#include <cuda_runtime.h>

// R2D2Head: B tasks (2048), s=25 support, d=640, 5-way, q=75 queries
#define NS 25
#define DQ 640
#define NWAY 5
#define NQ 75
#define RIDGE 50.0f
#define TASKS_MAX 2048

#define SR 640     // S smem row stride
#define ACOLS 33   // augmented matrix row stride (conflict-free columns)
#define WS 640     // W_T smem row stride in kernel B

__device__ float g_W[TASKS_MAX * NWAY * DQ];   // 26.2 MB scratch

// packed fp32x2 FMA (FFMA2) — only reachable via PTX
__device__ __forceinline__ void fma_f32x2(unsigned long long& acc,
                                          unsigned long long a,
                                          unsigned long long b)
{
    asm("fma.rn.f32x2 %0, %1, %2, %0;" : "+l"(acc) : "l"(a), "l"(b));
}

// ---------------- Kernel A: gram + solve + W ----------------
// smem: S 16000 | A 25*33=825 | SOL 200 | FLAG 4 -> 17032 floats (68.1 KB), 3 CTAs/SM
#define A_OFF_S    0
#define A_OFF_A    16000
#define A_OFF_SOL  16828
#define A_OFF_FLAG 17028
#define A_SMEM_FLOATS 17032

__global__ __launch_bounds__(256, 3)
void r2d2_prep(const float* __restrict__ support,
               const int* __restrict__ labels_raw)
{
    extern __shared__ float sm[];
    float* Ssm = sm + A_OFF_S;
    float* A   = sm + A_OFF_A;
    float* SOL = sm + A_OFF_SOL;
    int*  FLAG = (int*)(sm + A_OFF_FLAG);

    const int b = blockIdx.x;
    const int t = threadIdx.x;
    const int warp = t >> 5, lane = t & 31;

    // ---- label dtype sniff: parallel, one load latency ----
    if (warp == 0) {
        int lo = labels_raw[2 * lane];
        int hi = labels_raw[2 * lane + 1];
        bool ok = (hi == 0) && (lo >= 0) && (lo <= 4);
        unsigned m = __ballot_sync(0xffffffffu, ok);
        if (lane == 0) FLAG[0] = (m == 0xffffffffu) ? 1 : 0;
    }

    // ---- load S (25 x 640) via float4, streaming hint ----
    const float4* Sg4 = (const float4*)(support + (size_t)b * NS * DQ);
    float4* Ss4 = (float4*)Ssm;
    for (int idx = t; idx < NS * DQ / 4; idx += 256)
        Ss4[idx] = __ldcs(&Sg4[idx]);
    __syncthreads();

    const int lab_i64 = FLAG[0];

    // ---- gram: warp per 5x5 triangular tile, packed f32x2 FMA ----
    // (compiler free to unroll/pipeline the it-loop for load MLP)
    for (int tile = warp; tile < 15; tile += 8) {
        int ti = 0, rem = tile;
        while (rem >= 5 - ti) { rem -= 5 - ti; ++ti; }
        int tj = ti + rem;

        unsigned long long acc2[5][5];
        #pragma unroll
        for (int r = 0; r < 5; ++r)
            #pragma unroll
            for (int c = 0; c < 5; ++c) acc2[r][c] = 0ull;

        const float* Ri = Ssm + (5 * ti) * SR;
        const float* Rj = Ssm + (5 * tj) * SR;
        #pragma unroll 2
        for (int it = 0; it < 10; ++it) {       // 10 * 64 = 640 (2 floats/lane)
            int off = 2 * lane + 64 * it;
            unsigned long long av[5], bv[5];
            #pragma unroll
            for (int r = 0; r < 5; ++r)
                av[r] = *(const unsigned long long*)(Ri + r * SR + off);
            #pragma unroll
            for (int c = 0; c < 5; ++c)
                bv[c] = *(const unsigned long long*)(Rj + c * SR + off);
            #pragma unroll
            for (int r = 0; r < 5; ++r)
                #pragma unroll
                for (int c = 0; c < 5; ++c)
                    fma_f32x2(acc2[r][c], av[r], bv[c]);
        }
        #pragma unroll
        for (int r = 0; r < 5; ++r)
            #pragma unroll
            for (int c = 0; c < 5; ++c) {
                float2 p = *reinterpret_cast<float2*>(&acc2[r][c]);
                float v = p.x + p.y;
                v += __shfl_down_sync(0xffffffffu, v, 16);
                v += __shfl_down_sync(0xffffffffu, v, 8);
                v += __shfl_down_sync(0xffffffffu, v, 4);
                v += __shfl_down_sync(0xffffffffu, v, 2);
                v += __shfl_down_sync(0xffffffffu, v, 1);
                if (lane == 0) {
                    int i = 5 * ti + r, j = 5 * tj + c;
                    float g = v + (i == j ? RIDGE : 0.f);
                    A[i * ACOLS + j] = g;
                    A[j * ACOLS + i] = g;
                }
            }
    }
    // one-hot Y into columns 25..29
    if (t < 125) {
        int i = t / 5, w = t - i * 5;
        int base = b * NS + i;
        int lab = lab_i64 ? labels_raw[2 * base] : labels_raw[base];
        A[i * ACOLS + 25 + w] = (lab == w) ? 1.f : 0.f;
    }
    __syncthreads();

    // ---- solve: block-parallel Gauss-Jordan, fast divide ----
    {
        const int gi = t % 25;
        const int gj = t / 25;            // 0..9 active
        const bool act = (t < 250);
        for (int k = 0; k < NS; ++k) {
            float f = 0.f, pk0 = 0.f, pk1 = 0.f, pk2 = 0.f;
            if (act) {
                f   = __fdividef(A[gi * ACOLS + k], A[k * ACOLS + k]);
                pk0 = A[k * ACOLS + gj];
                pk1 = A[k * ACOLS + gj + 10];
                pk2 = A[k * ACOLS + gj + 20];
            }
            __syncthreads();
            if (act && gi != k) {
                A[gi * ACOLS + gj]      -= f * pk0;
                A[gi * ACOLS + gj + 10] -= f * pk1;
                A[gi * ACOLS + gj + 20] -= f * pk2;
            }
            __syncthreads();
        }
    }
    if (t < 125) {
        int i = t / 5, w = t - i * 5;
        SOL[i * 8 + w] = __fdividef(A[i * ACOLS + 25 + w], A[i * ACOLS + i]);
    }
    __syncthreads();

    // ---- W[w][d] = sum_s S[s][d] * sol[s][w]  -> global scratch ----
    {
        float* Wb = g_W + (size_t)b * NWAY * DQ;
        int d0 = t, d1 = t + 256, d2 = t + 512;
        bool h2 = (d2 < DQ);
        float a0[5], a1[5], a2[5];
        #pragma unroll
        for (int w = 0; w < 5; ++w) { a0[w] = 0.f; a1[w] = 0.f; a2[w] = 0.f; }
        for (int s = 0; s < NS; ++s) {
            float s0 = Ssm[s * SR + d0];
            float s1 = Ssm[s * SR + d1];
            float s2 = h2 ? Ssm[s * SR + d2] : 0.f;
            #pragma unroll
            for (int w = 0; w < 5; ++w) {
                float sv = SOL[s * 8 + w];
                a0[w] = fmaf(s0, sv, a0[w]);
                a1[w] = fmaf(s1, sv, a1[w]);
                a2[w] = fmaf(s2, sv, a2[w]);
            }
        }
        #pragma unroll
        for (int w = 0; w < 5; ++w) {
            Wb[w * DQ + d0] = a0[w];
            Wb[w * DQ + d1] = a1[w];
            if (h2) Wb[w * DQ + d2] = a2[w];
        }
    }
}

// ---------------- Kernel B: logits = Q @ W (64-reg, 4 CTAs/SM) ----------------
#define B_OFF_WT  0
#define B_OFF_LOG 3200
#define B_SMEM_FLOATS 3576

__global__ __launch_bounds__(256, 4)
void r2d2_logits(const float* __restrict__ query,
                 float* __restrict__ out)
{
    extern __shared__ float sm[];
    float* WT  = sm + B_OFF_WT;
    float* LOG = sm + B_OFF_LOG;

    const int b = blockIdx.x;
    const int t = threadIdx.x;
    const int warp = t >> 5, lane = t & 31;

    {
        const float4* Wg4 = (const float4*)(g_W + (size_t)b * NWAY * DQ);
        float4* Wt4 = (float4*)WT;
        for (int idx = t; idx < NWAY * DQ / 4; idx += 256)
            Wt4[idx] = Wg4[idx];
    }
    __syncthreads();

    const float4* Qb = (const float4*)(query + (size_t)b * NQ * DQ);
    for (int g = warp; g < 15; g += 8) {
        int r0 = g * 5;
        float acc[5][5];
        #pragma unroll
        for (int r = 0; r < 5; ++r)
            #pragma unroll
            for (int w = 0; w < 5; ++w) acc[r][w] = 0.f;

        #pragma unroll
        for (int it = 0; it < 5; ++it) {
            int d4 = lane + it * 32;
            float4 qv[5];
            #pragma unroll
            for (int r = 0; r < 5; ++r) qv[r] = __ldcs(&Qb[(r0 + r) * 160 + d4]);
            #pragma unroll
            for (int w = 0; w < 5; ++w) {
                float4 wv = *(const float4*)&WT[w * WS + d4 * 4];
                #pragma unroll
                for (int r = 0; r < 5; ++r) {
                    acc[r][w] = fmaf(qv[r].x, wv.x, acc[r][w]);
                    acc[r][w] = fmaf(qv[r].y, wv.y, acc[r][w]);
                    acc[r][w] = fmaf(qv[r].z, wv.z, acc[r][w]);
                    acc[r][w] = fmaf(qv[r].w, wv.w, acc[r][w]);
                }
            }
        }
        #pragma unroll
        for (int r = 0; r < 5; ++r)
            #pragma unroll
            for (int w = 0; w < 5; ++w) {
                float v = acc[r][w];
                v += __shfl_xor_sync(0xffffffffu, v, 16);
                v += __shfl_xor_sync(0xffffffffu, v, 8);
                v += __shfl_xor_sync(0xffffffffu, v, 4);
                v += __shfl_xor_sync(0xffffffffu, v, 2);
                v += __shfl_xor_sync(0xffffffffu, v, 1);
                acc[r][w] = v;
            }
        if (lane == 0) {
            #pragma unroll
            for (int r = 0; r < 5; ++r)
                #pragma unroll
                for (int w = 0; w < 5; ++w)
                    LOG[(r0 + r) * 5 + w] = acc[r][w];
        }
    }
    __syncthreads();

    for (int idx = t; idx < NQ * NWAY; idx += 256)
        out[(size_t)b * (NQ * NWAY) + idx] = LOG[idx];
}

extern "C" void kernel_launch(void* const* d_in, const int* in_sizes, int n_in,
                              void* d_out, int out_size)
{
    const float* query   = (const float*)d_in[0];
    const float* support = (const float*)d_in[1];
    const int* labels    = (const int*)d_in[2];
    float* out = (float*)d_out;

    int tasks = in_sizes[1] / (NS * DQ);
    if (tasks > TASKS_MAX) tasks = TASKS_MAX;

    size_t smemA = (size_t)A_SMEM_FLOATS * sizeof(float);
    cudaFuncSetAttribute(r2d2_prep,
                         cudaFuncAttributeMaxDynamicSharedMemorySize, (int)smemA);
    size_t smemB = (size_t)B_SMEM_FLOATS * sizeof(float);

    r2d2_prep<<<tasks, 256, smemA>>>(support, labels);
    r2d2_logits<<<tasks, 256, smemB>>>(query, out);
}

// round 11
// speedup vs baseline: 1.2026x; 1.0472x over previous
#include <cuda_runtime.h>

// R2D2Head fused: B tasks (2048), s=25 support, d=640, 5-way, q=75 queries
#define NS 25
#define DQ 640
#define NWAY 5
#define NQ 75
#define RIDGE 50.0f

#define SR 640     // S smem row stride
#define ACOLS 33   // augmented matrix row stride (conflict-free columns)
#define WS 640     // W_T smem row stride (reuses front of S region)

// shared memory layout (floats)
#define OFF_S    0          // 25*640 = 16000 ; first 3200 reused as WT in B-phase
#define OFF_A    16000      // 25*33 = 825
#define OFF_SOL  16828      // 200
#define OFF_LOG  17028      // 376
#define OFF_FLAG 17404      // 4
#define SMEM_FLOATS 17408   // 69632 B -> 3 CTAs/SM

// packed fp32x2 FMA (FFMA2) — only reachable via PTX
__device__ __forceinline__ void fma_f32x2(unsigned long long& acc,
                                          unsigned long long a,
                                          unsigned long long b)
{
    asm("fma.rn.f32x2 %0, %1, %2, %0;" : "+l"(acc) : "l"(a), "l"(b));
}

__global__ __launch_bounds__(256, 3)
void r2d2_fused(const float* __restrict__ query,
                const float* __restrict__ support,
                const int* __restrict__ labels_raw,
                float* __restrict__ out)
{
    extern __shared__ float sm[];
    float* Ssm = sm + OFF_S;
    float* A   = sm + OFF_A;
    float* SOL = sm + OFF_SOL;
    float* LOG = sm + OFF_LOG;
    float* WT  = sm + OFF_S;          // alias: S region reused after W phase
    int*  FLAG = (int*)(sm + OFF_FLAG);

    const int b = blockIdx.x;
    const int t = threadIdx.x;
    const int warp = t >> 5, lane = t & 31;

    // ---- Phase 0: label dtype sniff (parallel, one load latency) ----
    if (warp == 0) {
        int lo = labels_raw[2 * lane];
        int hi = labels_raw[2 * lane + 1];
        bool ok = (hi == 0) && (lo >= 0) && (lo <= 4);
        unsigned m = __ballot_sync(0xffffffffu, ok);
        if (lane == 0) FLAG[0] = (m == 0xffffffffu) ? 1 : 0;
    }

    // ---- Phase 1: load S (25 x 640) via float4, streaming hint ----
    const float4* Sg4 = (const float4*)(support + (size_t)b * NS * DQ);
    float4* Ss4 = (float4*)Ssm;
    for (int idx = t; idx < NS * DQ / 4; idx += 256)
        Ss4[idx] = __ldcs(&Sg4[idx]);
    __syncthreads();

    const int lab_i64 = FLAG[0];

    // ---- Phase 2: gram, warp per 5x5 triangular tile, f32x2 FMA ----
    for (int tile = warp; tile < 15; tile += 8) {
        int ti = 0, rem = tile;
        while (rem >= 5 - ti) { rem -= 5 - ti; ++ti; }
        int tj = ti + rem;

        unsigned long long acc2[5][5];
        #pragma unroll
        for (int r = 0; r < 5; ++r)
            #pragma unroll
            for (int c = 0; c < 5; ++c) acc2[r][c] = 0ull;

        const float* Ri = Ssm + (5 * ti) * SR;
        const float* Rj = Ssm + (5 * tj) * SR;
        #pragma unroll 2
        for (int it = 0; it < 10; ++it) {      // 10 * 64 = 640
            int off = 2 * lane + 64 * it;
            unsigned long long av[5], bv[5];
            #pragma unroll
            for (int r = 0; r < 5; ++r)
                av[r] = *(const unsigned long long*)(Ri + r * SR + off);
            #pragma unroll
            for (int c = 0; c < 5; ++c)
                bv[c] = *(const unsigned long long*)(Rj + c * SR + off);
            #pragma unroll
            for (int r = 0; r < 5; ++r)
                #pragma unroll
                for (int c = 0; c < 5; ++c)
                    fma_f32x2(acc2[r][c], av[r], bv[c]);
        }
        #pragma unroll
        for (int r = 0; r < 5; ++r)
            #pragma unroll
            for (int c = 0; c < 5; ++c) {
                float2 p = *reinterpret_cast<float2*>(&acc2[r][c]);
                float v = p.x + p.y;
                v += __shfl_down_sync(0xffffffffu, v, 16);
                v += __shfl_down_sync(0xffffffffu, v, 8);
                v += __shfl_down_sync(0xffffffffu, v, 4);
                v += __shfl_down_sync(0xffffffffu, v, 2);
                v += __shfl_down_sync(0xffffffffu, v, 1);
                if (lane == 0) {
                    int i = 5 * ti + r, j = 5 * tj + c;
                    float g = v + (i == j ? RIDGE : 0.f);
                    A[i * ACOLS + j] = g;
                    A[j * ACOLS + i] = g;
                }
            }
    }
    if (t < 125) {                              // one-hot Y cols 25..29
        int i = t / 5, w = t - i * 5;
        int base = b * NS + i;
        int lab = lab_i64 ? labels_raw[2 * base] : labels_raw[base];
        A[i * ACOLS + 25 + w] = (lab == w) ? 1.f : 0.f;
    }
    __syncthreads();

    // ---- Phase 3: block-parallel Gauss-Jordan (SPD + ridge), fast div ----
    {
        const int gi = t % 25;
        const int gj = t / 25;
        const bool act = (t < 250);
        for (int k = 0; k < NS; ++k) {
            float f = 0.f, pk0 = 0.f, pk1 = 0.f, pk2 = 0.f;
            if (act) {
                f   = __fdividef(A[gi * ACOLS + k], A[k * ACOLS + k]);
                pk0 = A[k * ACOLS + gj];
                pk1 = A[k * ACOLS + gj + 10];
                pk2 = A[k * ACOLS + gj + 20];
            }
            __syncthreads();
            if (act && gi != k) {
                A[gi * ACOLS + gj]      -= f * pk0;
                A[gi * ACOLS + gj + 10] -= f * pk1;
                A[gi * ACOLS + gj + 20] -= f * pk2;
            }
            __syncthreads();
        }
    }
    if (t < 125) {
        int i = t / 5, w = t - i * 5;
        SOL[i * 8 + w] = __fdividef(A[i * ACOLS + 25 + w], A[i * ACOLS + i]);
    }
    __syncthreads();

    // ---- Phase 4: W in registers (reads all of S), then overwrite S front ----
    float a0[5], a1[5], a2[5];
    {
        int d0 = t, d1 = t + 256, d2 = t + 512;
        bool h2 = (d2 < DQ);                    // t < 128
        #pragma unroll
        for (int w = 0; w < 5; ++w) { a0[w] = 0.f; a1[w] = 0.f; a2[w] = 0.f; }
        for (int s = 0; s < NS; ++s) {
            float s0 = Ssm[s * SR + d0];
            float s1 = Ssm[s * SR + d1];
            float s2 = h2 ? Ssm[s * SR + d2] : 0.f;
            #pragma unroll
            for (int w = 0; w < 5; ++w) {
                float sv = SOL[s * 8 + w];
                a0[w] = fmaf(s0, sv, a0[w]);
                a1[w] = fmaf(s1, sv, a1[w]);
                a2[w] = fmaf(s2, sv, a2[w]);
            }
        }
        __syncthreads();                        // all S reads done before overwrite
        #pragma unroll
        for (int w = 0; w < 5; ++w) {
            WT[w * WS + d0] = a0[w];
            WT[w * WS + d1] = a1[w];
            if (h2) WT[w * WS + d2] = a2[w];
        }
    }
    __syncthreads();

    // ---- Phase 5: logits = Q @ W, warp per 5 query rows, float4 streams ----
    const float4* Qb = (const float4*)(query + (size_t)b * NQ * DQ);
    for (int g = warp; g < 15; g += 8) {
        int r0 = g * 5;
        float acc[5][5];
        #pragma unroll
        for (int r = 0; r < 5; ++r)
            #pragma unroll
            for (int w = 0; w < 5; ++w) acc[r][w] = 0.f;

        #pragma unroll
        for (int it = 0; it < 5; ++it) {
            int d4 = lane + it * 32;
            float4 qv[5];
            #pragma unroll
            for (int r = 0; r < 5; ++r) qv[r] = __ldcs(&Qb[(r0 + r) * 160 + d4]);
            #pragma unroll
            for (int w = 0; w < 5; ++w) {
                float4 wv = *(const float4*)&WT[w * WS + d4 * 4];
                #pragma unroll
                for (int r = 0; r < 5; ++r) {
                    acc[r][w] = fmaf(qv[r].x, wv.x, acc[r][w]);
                    acc[r][w] = fmaf(qv[r].y, wv.y, acc[r][w]);
                    acc[r][w] = fmaf(qv[r].z, wv.z, acc[r][w]);
                    acc[r][w] = fmaf(qv[r].w, wv.w, acc[r][w]);
                }
            }
        }
        #pragma unroll
        for (int r = 0; r < 5; ++r)
            #pragma unroll
            for (int w = 0; w < 5; ++w) {
                float v = acc[r][w];
                v += __shfl_xor_sync(0xffffffffu, v, 16);
                v += __shfl_xor_sync(0xffffffffu, v, 8);
                v += __shfl_xor_sync(0xffffffffu, v, 4);
                v += __shfl_xor_sync(0xffffffffu, v, 2);
                v += __shfl_xor_sync(0xffffffffu, v, 1);
                acc[r][w] = v;
            }
        if (lane == 0) {
            #pragma unroll
            for (int r = 0; r < 5; ++r)
                #pragma unroll
                for (int w = 0; w < 5; ++w)
                    LOG[(r0 + r) * 5 + w] = acc[r][w];
        }
    }
    __syncthreads();

    // ---- Phase 6: coalesced output store (375 entries, strided) ----
    for (int idx = t; idx < NQ * NWAY; idx += 256)
        out[(size_t)b * (NQ * NWAY) + idx] = LOG[idx];
}

extern "C" void kernel_launch(void* const* d_in, const int* in_sizes, int n_in,
                              void* d_out, int out_size)
{
    const float* query   = (const float*)d_in[0];
    const float* support = (const float*)d_in[1];
    const int* labels    = (const int*)d_in[2];
    float* out = (float*)d_out;

    int tasks = in_sizes[1] / (NS * DQ);   // 2048

    size_t smem = (size_t)SMEM_FLOATS * sizeof(float);
    cudaFuncSetAttribute(r2d2_fused,
                         cudaFuncAttributeMaxDynamicSharedMemorySize, (int)smem);

    r2d2_fused<<<tasks, 256, smem>>>(query, support, labels, out);
}